// round 1
// baseline (speedup 1.0000x reference)
#include <cuda_runtime.h>

// DeepPoly ReLU relaxation, elementwise over N floats.
// inputs: lb, ub, alpha (fp32, N each). output: [out_lb (N) | out_ub (N)] fp32.
//
// Pure HBM-bound: 3N reads + 2N writes = 20 B/elem.
// float4 vectorized, one quad per thread.

__global__ __launch_bounds__(256) void verify_relu_kernel(
    const float4* __restrict__ lb4,
    const float4* __restrict__ ub4,
    const float4* __restrict__ al4,
    float4* __restrict__ olb4,
    float4* __restrict__ oub4,
    int n4)
{
    int i = blockIdx.x * blockDim.x + threadIdx.x;
    if (i >= n4) return;

    float4 lb = lb4[i];
    float4 ub = ub4[i];
    float4 al = al4[i];

    float4 olb, oub;

    #pragma unroll
    for (int k = 0; k < 4; k++) {
        float l = (&lb.x)[k];
        float u = (&ub.x)[k];
        float a = (&al.x)[k];

        float ca    = fminf(fmaxf(a, 0.0f), 1.0f);
        float slope = fmaxf(u / (u - l), 0.0f);

        // upper constraint
        float uc_diag = (l > 0.0f) ? 1.0f : slope;
        float uc_bias = (l > 0.0f) ? 0.0f : (-(slope * l));
        // lower constraint
        float lc_diag = (u < 0.0f) ? 0.0f : ca;

        (&olb.x)[k] = l * lc_diag;
        (&oub.x)[k] = fmaf(u, uc_diag, uc_bias);
    }

    olb4[i] = olb;
    oub4[i] = oub;
}

extern "C" void kernel_launch(void* const* d_in, const int* in_sizes, int n_in,
                              void* d_out, int out_size) {
    const float* lb    = (const float*)d_in[0];
    const float* ub    = (const float*)d_in[1];
    const float* alpha = (const float*)d_in[2];
    float* out = (float*)d_out;

    int n  = in_sizes[0];        // 16777216
    int n4 = n / 4;              // divisible by 4

    float* out_lb = out;
    float* out_ub = out + n;

    int threads = 256;
    int blocks  = (n4 + threads - 1) / threads;

    verify_relu_kernel<<<blocks, threads>>>(
        (const float4*)lb, (const float4*)ub, (const float4*)alpha,
        (float4*)out_lb, (float4*)out_ub, n4);
}